// round 15
// baseline (speedup 1.0000x reference)
#include <cuda_runtime.h>
#include <cuda_bf16.h>

typedef unsigned long long u64;
typedef unsigned int u32;

// ---------------- scratch (static device globals; no runtime alloc) ----------
__device__ float g_X [64*64*4096];    // 64 MB: pre-activations X[t,b,4096]
__device__ float g_H [64*64*1024];    // 16 MB: hidden history H[t,b,1024]
__device__ float g_Q [64*64*1024];    // 16 MB: encoder queries
__device__ float g_QD[64*64*1024];    // 16 MB: decoder queries
__device__ float g_E [64*64*512];     //  8 MB: enc scores -> sc -> alpha (in place)
__device__ float g_ED[64*64*64];      //  1 MB: dec scores -> alpha (in place)
__device__ float g_c [64*1024];       // cell state
__device__ float g_P [8*64*4096];     //  8 MB: K-split partials, P[ks][b][4096]
__device__ __nv_bfloat16 g_WHI[4096*1024];  // 8 MB: W_hh bf16 hi
__device__ __nv_bfloat16 g_WLO[4096*1024];  // 8 MB: W_hh bf16 lo (residual)
__device__ __nv_bfloat16 g_hHI[64*1024];    // h_prev bf16 hi
__device__ __nv_bfloat16 g_hLO[64*1024];    // h_prev bf16 lo

// ---------------- f32x2 packed helpers --------------------------------------
__device__ __forceinline__ void fma2(u64& a, u64 x, u64 y){
    asm("fma.rn.f32x2 %0, %1, %2, %0;" : "+l"(a) : "l"(x), "l"(y));
}
__device__ __forceinline__ u64 dup2(float f){
    u32 u = __float_as_uint(f);
    u64 r; asm("mov.b64 %0, {%1, %1};" : "=l"(r) : "r"(u));
    return r;
}
__device__ __forceinline__ float lo32(u64 v){ return __uint_as_float((u32)v); }
__device__ __forceinline__ float hi32(u64 v){ return __uint_as_float((u32)(v>>32)); }

__device__ __forceinline__ u32 smem_u32(const void* p){
    u32 a; asm("{ .reg .u64 t; cvta.to.shared.u64 t, %1; cvt.u32.u64 %0, t; }"
               : "=r"(a) : "l"(p));
    return a;
}

// ---------------- legacy-HMMA helpers (mma.sync, valid on compute_103) -------
#define LDSM4(r, a) \
    asm volatile("ldmatrix.sync.aligned.m8n8.x4.shared.b16 {%0,%1,%2,%3}, [%4];" \
        : "=r"((r)[0]), "=r"((r)[1]), "=r"((r)[2]), "=r"((r)[3]) : "r"(a))

#define MMA16816(d, a, b) \
    asm volatile("mma.sync.aligned.m16n8k16.row.col.f32.bf16.bf16.f32 " \
        "{%0,%1,%2,%3}, {%4,%5,%6,%7}, {%8,%9}, {%0,%1,%2,%3};" \
        : "+f"((d)[0]), "+f"((d)[1]), "+f"((d)[2]), "+f"((d)[3]) \
        : "r"((a)[0]), "r"((a)[1]), "r"((a)[2]), "r"((a)[3]), \
          "r"((b)[0]), "r"((b)[1]))

// ---------------- bf16 hi/lo conversion -------------------------------------
__global__ void __launch_bounds__(256) conv_pair(
    const float* __restrict__ src, __nv_bfloat16* __restrict__ hi,
    __nv_bfloat16* __restrict__ lo, int n4)
{
    int i = blockIdx.x * 256 + threadIdx.x;
    if (i >= n4) return;
    float4 v = ((const float4*)src)[i];
    #pragma unroll
    for (int j = 0; j < 4; j++) {
        float f = (&v.x)[j];
        __nv_bfloat16 h = __float2bfloat16(f);
        hi[i*4 + j] = h;
        lo[i*4 + j] = __float2bfloat16(f - __bfloat162float(h));
    }
}

// ---------------- HMMA LSTM step GEMM (v3: 8 warps, K-split 8) ---------------
// G^T[4096,64] = W_hh[4096,1024] @ h_prev^T, split-bf16 (hh + hl + lh).
// grid (32 m-tiles, 8 K-splits) = 256 blocks (~1.7/SM -> overlap), 256 thr.
// Block tile M=128, N=64, K-chunk 128 (4 sub-chunks of 32 k).
// Warp tile M=16, N=64 (8 n8). Epilogue transposes via SMEM so partials
// land coalesced as P[ks][b][4096].
#define AP 40   // SMEM pitch (bf16) = 32 k + 16B pad
#define SM_AHI 0
#define SM_ALO (128*AP)
#define SM_BHI (256*AP)
#define SM_BLO (256*AP + 64*AP)
#define CT_P 66                          // Ct pitch (floats); 128*66*4 = 33792 B

__global__ void __launch_bounds__(256,2) hmma_step(
    const __nv_bfloat16* __restrict__ Whi, const __nv_bfloat16* __restrict__ Wlo,
    const __nv_bfloat16* __restrict__ hhi, const __nv_bfloat16* __restrict__ hlo,
    float* __restrict__ P)
{
    __shared__ __align__(16) char smraw[33792];   // max(30720 operands, 33792 Ct)
    __nv_bfloat16* Ahi = (__nv_bfloat16*)smraw + SM_AHI;
    __nv_bfloat16* Alo = (__nv_bfloat16*)smraw + SM_ALO;
    __nv_bfloat16* Bhi = (__nv_bfloat16*)smraw + SM_BHI;
    __nv_bfloat16* Blo = (__nv_bfloat16*)smraw + SM_BLO;

    const int tid = threadIdx.x;
    const int w = tid >> 5, l = tid & 31;
    const int m0 = blockIdx.x * 128;
    const int ks = blockIdx.y;
    const int kb = ks * 128;

    float acc[8][4];
    #pragma unroll
    for (int nj = 0; nj < 8; nj++)
        #pragma unroll
        for (int q = 0; q < 4; q++) acc[nj][q] = 0.f;

    // A staging: thread covers row = tid>>1, uint4 positions half*2, half*2+1
    const int arow = tid >> 1, ahalf = tid & 1;
    const uint4* gAh = (const uint4*)(Whi + (long)(m0 + arow)*1024 + kb);
    const uint4* gAl = (const uint4*)(Wlo + (long)(m0 + arow)*1024 + kb);
    uint4* sAh = (uint4*)(Ahi + arow*AP);
    uint4* sAl = (uint4*)(Alo + arow*AP);
    // B staging: thread covers brow = tid>>2, uint4 position bp (hi and lo)
    const int brow = tid >> 2, bp = tid & 3;
    const uint4* gBh = (const uint4*)(hhi + (long)brow*1024 + kb);
    const uint4* gBl = (const uint4*)(hlo + (long)brow*1024 + kb);
    uint4* sBh = (uint4*)(Bhi + brow*AP);
    uint4* sBl = (uint4*)(Blo + brow*AP);

    // ldmatrix source offsets (within-k16 pattern, same as R12/R13)
    const int a_r = (l & 15);                 // + w*16
    const int a_c = (l & 16) ? 8 : 0;
    const int b_r = (l & 7);
    const int b_c = (l & 8) ? 8 : 0;

    uint4 pAh[2], pAl[2], pBh, pBl;
    pAh[0] = gAh[ahalf*2]; pAh[1] = gAh[ahalf*2 + 1];
    pAl[0] = gAl[ahalf*2]; pAl[1] = gAl[ahalf*2 + 1];
    pBh = gBh[bp]; pBl = gBl[bp];

    for (int kc = 0; kc < 4; kc++) {
        __syncthreads();
        sAh[ahalf*2] = pAh[0]; sAh[ahalf*2 + 1] = pAh[1];
        sAl[ahalf*2] = pAl[0]; sAl[ahalf*2 + 1] = pAl[1];
        sBh[bp] = pBh; sBl[bp] = pBl;
        __syncthreads();
        if (kc + 1 < 4) {
            int base = (kc + 1) * 4;
            pAh[0] = gAh[base + ahalf*2]; pAh[1] = gAh[base + ahalf*2 + 1];
            pAl[0] = gAl[base + ahalf*2]; pAl[1] = gAl[base + ahalf*2 + 1];
            pBh = gBh[base + bp]; pBl = gBl[base + bp];
        }
        #pragma unroll
        for (int k16 = 0; k16 < 2; k16++) {
            const int k0 = k16 * 16;
            u32 ah[4], al[4], bh[8][2], bl[8][2];
            {
                int row = w*16 + a_r;
                LDSM4(ah, smem_u32(Ahi + row*AP + k0 + a_c));
                LDSM4(al, smem_u32(Alo + row*AP + k0 + a_c));
            }
            #pragma unroll
            for (int jj = 0; jj < 4; jj++) {
                int n = ((l < 16) ? jj*2 : jj*2+1)*8 + b_r;
                u32 r4[4];
                LDSM4(r4, smem_u32(Bhi + n*AP + k0 + b_c));
                bh[jj*2][0] = r4[0]; bh[jj*2][1] = r4[1];
                bh[jj*2+1][0] = r4[2]; bh[jj*2+1][1] = r4[3];
                LDSM4(r4, smem_u32(Blo + n*AP + k0 + b_c));
                bl[jj*2][0] = r4[0]; bl[jj*2][1] = r4[1];
                bl[jj*2+1][0] = r4[2]; bl[jj*2+1][1] = r4[3];
            }
            #pragma unroll
            for (int nj = 0; nj < 8; nj++) {
                MMA16816(acc[nj], ah, bh[nj]);
                MMA16816(acc[nj], ah, bl[nj]);
                MMA16816(acc[nj], al, bh[nj]);
            }
        }
    }

    // epilogue: transpose via SMEM -> coalesced P[ks][b][m]
    __syncthreads();
    float* Ct = (float*)smraw;   // [128][CT_P]
    {
        int row = w*16 + (l >> 2);
        #pragma unroll
        for (int nj = 0; nj < 8; nj++) {
            int colb = nj*8 + (l & 3)*2;
            *(float2*)&Ct[row*CT_P + colb]     = make_float2(acc[nj][0], acc[nj][1]);
            *(float2*)&Ct[(row+8)*CT_P + colb] = make_float2(acc[nj][2], acc[nj][3]);
        }
    }
    __syncthreads();
    {
        int b = tid >> 2, q = tid & 3;
        float* dst = P + ((long)ks*64 + b)*4096 + m0 + q*32;
        #pragma unroll
        for (int i = 0; i < 8; i++) {
            int m = q*32 + i*4;
            float4 v;
            v.x = Ct[(m+0)*CT_P + b];
            v.y = Ct[(m+1)*CT_P + b];
            v.z = Ct[(m+2)*CT_P + b];
            v.w = Ct[(m+3)*CT_P + b];
            *(float4*)(dst + i*4) = v;
        }
    }
}

// ---------------- LSTM fin: reduce 8 partials + elementwise + h hi/lo --------
__global__ void __launch_bounds__(128) lstm_fin(
    const float* __restrict__ P, const float* __restrict__ X,
    const float* __restrict__ cprev,
    float* __restrict__ cnew, float* __restrict__ Hout,
    float* __restrict__ outp,
    __nv_bfloat16* __restrict__ hHI, __nv_bfloat16* __restrict__ hLO)
{
    int idx = blockIdx.x * 128 + threadIdx.x;   // 0..16383
    int b  = idx >> 8;
    int dq = (idx & 255) * 4;

    float4 g[4];
    #pragma unroll
    for (int gate = 0; gate < 4; gate++) {
        long off = (long)b * 4096 + gate * 1024 + dq;
        float4 v = *(const float4*)&X[off];
        #pragma unroll
        for (int ks = 0; ks < 8; ks++) {
            float4 p = *(const float4*)&P[(long)ks * (64*4096) + off];
            v.x += p.x; v.y += p.y; v.z += p.z; v.w += p.w;
        }
        g[gate] = v;
    }
    float4 co = *(const float4*)&cprev[b*1024 + dq];
    float4 cn, hn;
    #pragma unroll
    for (int j = 0; j < 4; j++) {
        float iv = (&g[0].x)[j], fv = (&g[1].x)[j];
        float gv = (&g[2].x)[j], ov = (&g[3].x)[j];
        float si = 1.f / (1.f + __expf(-iv));
        float sf = 1.f / (1.f + __expf(-fv));
        float so = 1.f / (1.f + __expf(-ov));
        float tg = 2.f / (1.f + __expf(-2.f*gv)) - 1.f;
        float cc = sf * (&co.x)[j] + si * tg;
        float tc = 2.f / (1.f + __expf(-2.f*cc)) - 1.f;
        (&cn.x)[j] = cc;
        (&hn.x)[j] = so * tc;
    }
    *(float4*)&cnew[b*1024 + dq] = cn;
    *(float4*)&Hout[b*1024 + dq] = hn;
    *(float4*)&outp[(long)b*3072 + dq] = hn;
    #pragma unroll
    for (int j = 0; j < 4; j++) {
        float hv = (&hn.x)[j];
        __nv_bfloat16 h = __float2bfloat16(hv);
        hHI[b*1024 + dq + j] = h;
        hLO[b*1024 + dq + j] = __float2bfloat16(hv - __bfloat162float(h));
    }
}

// ---------------- wide GEMM (R7-proven) --------------------------------------
template<bool GATHER, bool BNN>
__global__ void __launch_bounds__(256) gemm_wide(
    const float* __restrict__ A, long lda, const int* __restrict__ ridx,
    const float* __restrict__ B, long ldb,
    float* __restrict__ C, long ldc, int K,
    const float* __restrict__ bias1, const float* __restrict__ bias2,
    long bsA, long bsB, long bsC)
{
    __shared__ float At[16][68];
    __shared__ float Bt[16][260];
    const int tid = threadIdx.x;
    const int tx = tid & 31;
    const int ty = tid >> 5;
    const int n0 = blockIdx.x * 256;
    const int m0 = blockIdx.y * 64;
    const long z = blockIdx.z;

    const int arow = tid >> 2, akq = tid & 3;
    const float* Arow;
    {
        const float* Ab = A + z * bsA;
        long mrow = m0 + arow;
        if (GATHER) mrow = ridx[mrow];
        Arow = Ab + mrow * lda + akq * 4;
    }
    const int brow = tid >> 1, bq = tid & 1;
    const float* Brow0 = nullptr; const float* Brow1 = nullptr;
    const int bk = tid >> 4, bn = tid & 15;
    const float* Bk = nullptr;
    {
        const float* Bb = B + z * bsB;
        if (BNN) Bk = Bb + (long)bk * ldb + n0 + bn * 16;
        else {
            Brow0 = Bb + (long)(n0 + brow)       * ldb + bq * 8;
            Brow1 = Bb + (long)(n0 + brow + 128) * ldb + bq * 8;
        }
    }

    u64 acc[4][8];
    #pragma unroll
    for (int i = 0; i < 4; i++)
        #pragma unroll
        for (int j = 0; j < 8; j++) acc[i][j] = 0ull;

    float4 ra = *(const float4*)Arow;
    float4 pb0, pb1, pb2, pb3;
    if (BNN) {
        pb0 = *(const float4*)(Bk);
        pb1 = *(const float4*)(Bk + 4);
        pb2 = *(const float4*)(Bk + 8);
        pb3 = *(const float4*)(Bk + 12);
    } else {
        pb0 = *(const float4*)(Brow0);
        pb1 = *(const float4*)(Brow0 + 4);
        pb2 = *(const float4*)(Brow1);
        pb3 = *(const float4*)(Brow1 + 4);
    }

    for (int k0 = 0; k0 < K; k0 += 16) {
        __syncthreads();
        At[akq*4+0][arow] = ra.x;
        At[akq*4+1][arow] = ra.y;
        At[akq*4+2][arow] = ra.z;
        At[akq*4+3][arow] = ra.w;
        if (BNN) {
            *(float4*)&Bt[bk][bn*16 + 0]  = pb0;
            *(float4*)&Bt[bk][bn*16 + 4]  = pb1;
            *(float4*)&Bt[bk][bn*16 + 8]  = pb2;
            *(float4*)&Bt[bk][bn*16 + 12] = pb3;
        } else {
            Bt[bq*8+0][brow] = pb0.x; Bt[bq*8+1][brow] = pb0.y;
            Bt[bq*8+2][brow] = pb0.z; Bt[bq*8+3][brow] = pb0.w;
            Bt[bq*8+4][brow] = pb1.x; Bt[bq*8+5][brow] = pb1.y;
            Bt[bq*8+6][brow] = pb1.z; Bt[bq*8+7][brow] = pb1.w;
            Bt[bq*8+0][brow+128] = pb2.x; Bt[bq*8+1][brow+128] = pb2.y;
            Bt[bq*8+2][brow+128] = pb2.z; Bt[bq*8+3][brow+128] = pb2.w;
            Bt[bq*8+4][brow+128] = pb3.x; Bt[bq*8+5][brow+128] = pb3.y;
            Bt[bq*8+6][brow+128] = pb3.z; Bt[bq*8+7][brow+128] = pb3.w;
        }
        __syncthreads();
        if (k0 + 16 < K) {
            ra = *(const float4*)(Arow + k0 + 16);
            if (BNN) {
                const float* p = Bk + (long)(k0 + 16) * ldb;
                pb0 = *(const float4*)(p);
                pb1 = *(const float4*)(p + 4);
                pb2 = *(const float4*)(p + 8);
                pb3 = *(const float4*)(p + 12);
            } else {
                pb0 = *(const float4*)(Brow0 + k0 + 16);
                pb1 = *(const float4*)(Brow0 + k0 + 20);
                pb2 = *(const float4*)(Brow1 + k0 + 16);
                pb3 = *(const float4*)(Brow1 + k0 + 20);
            }
        }
        #pragma unroll
        for (int k = 0; k < 16; k++) {
            u64 a0 = *(const u64*)&At[k][ty*8];
            u64 a1 = *(const u64*)&At[k][ty*8+2];
            u64 a2 = *(const u64*)&At[k][ty*8+4];
            u64 a3 = *(const u64*)&At[k][ty*8+6];
            #pragma unroll
            for (int j = 0; j < 8; j++) {
                u64 bd = dup2(Bt[k][tx + 32*j]);
                fma2(acc[0][j], a0, bd);
                fma2(acc[1][j], a1, bd);
                fma2(acc[2][j], a2, bd);
                fma2(acc[3][j], a3, bd);
            }
        }
    }

    float bn8[8];
    #pragma unroll
    for (int j = 0; j < 8; j++) {
        int n = n0 + tx + 32*j;
        float v = 0.f;
        if (bias1) v += bias1[n];
        if (bias2) v += bias2[n];
        bn8[j] = v;
    }
    float* Cb = C + z * bsC;
    #pragma unroll
    for (int i = 0; i < 4; i++) {
        long r = m0 + ty*8 + 2*i;
        #pragma unroll
        for (int j = 0; j < 8; j++) {
            int n = n0 + tx + 32*j;
            Cb[r*ldc + n]     = lo32(acc[i][j]) + bn8[j];
            Cb[(r+1)*ldc + n] = hi32(acc[i][j]) + bn8[j];
        }
    }
}

// ---------------- small 64x64 NT/NN GEMM for ED / cd -------------------------
template<bool BNN>
__global__ void __launch_bounds__(256) gemm64(
    const float* __restrict__ A, long lda,
    const float* __restrict__ B, long ldb,
    float* __restrict__ C, long ldc, int K,
    long bsA, long bsB, long bsC)
{
    __shared__ float At[16][68];
    __shared__ float Bt[16][68];
    const int tid = threadIdx.x;
    const int tx = tid & 15, ty = tid >> 4;
    const int m0 = blockIdx.y * 64;
    const int n0 = blockIdx.x * 64;
    const long z = blockIdx.z;

    const int arow = tid >> 2, akq = tid & 3;
    const float* Arow = A + z*bsA + (long)(m0 + arow)*lda + akq*4;
    const float* Brow;
    int bk = 0, bnq = 0, brow = 0, bkq = 0;
    {
        const float* Bb = B + z * bsB;
        if (BNN) { bk = tid >> 4; bnq = tid & 15; Brow = Bb + (long)bk * ldb + n0 + bnq * 4; }
        else     { brow = tid >> 2; bkq = tid & 3; Brow = Bb + (long)(n0 + brow) * ldb + bkq * 4; }
    }

    u64 acc[2][4];
    #pragma unroll
    for (int p = 0; p < 2; p++)
        #pragma unroll
        for (int j = 0; j < 4; j++) acc[p][j] = 0ull;

    float4 ra = *(const float4*)(Arow);
    float4 rb = *(const float4*)(Brow);

    for (int k0 = 0; k0 < K; k0 += 16) {
        __syncthreads();
        At[akq*4+0][arow] = ra.x;
        At[akq*4+1][arow] = ra.y;
        At[akq*4+2][arow] = ra.z;
        At[akq*4+3][arow] = ra.w;
        if (BNN) {
            *(float4*)&Bt[bk][bnq*4] = rb;
        } else {
            Bt[bkq*4+0][brow] = rb.x;
            Bt[bkq*4+1][brow] = rb.y;
            Bt[bkq*4+2][brow] = rb.z;
            Bt[bkq*4+3][brow] = rb.w;
        }
        __syncthreads();
        if (k0 + 16 < K) {
            ra = *(const float4*)(Arow + k0 + 16);
            rb = BNN ? *(const float4*)(Brow + (long)(k0 + 16) * ldb)
                     : *(const float4*)(Brow + k0 + 16);
        }
        #pragma unroll
        for (int k = 0; k < 16; k++) {
            u64 a01 = *(const u64*)&At[k][ty*4];
            u64 a23 = *(const u64*)&At[k][ty*4+2];
            float4 bv = *(const float4*)&Bt[k][tx*4];
            u64 b0 = dup2(bv.x), b1 = dup2(bv.y), b2 = dup2(bv.z), b3 = dup2(bv.w);
            fma2(acc[0][0], a01, b0); fma2(acc[1][0], a23, b0);
            fma2(acc[0][1], a01, b1); fma2(acc[1][1], a23, b1);
            fma2(acc[0][2], a01, b2); fma2(acc[1][2], a23, b2);
            fma2(acc[0][3], a01, b3); fma2(acc[1][3], a23, b3);
        }
    }

    float* Cb = C + z * bsC;
    #pragma unroll
    for (int p = 0; p < 2; p++) {
        long mr = m0 + ty*4 + 2*p;
        float4 r0, r1;
        r0.x = lo32(acc[p][0]); r1.x = hi32(acc[p][0]);
        r0.y = lo32(acc[p][1]); r1.y = hi32(acc[p][1]);
        r0.z = lo32(acc[p][2]); r1.z = hi32(acc[p][2]);
        r0.w = lo32(acc[p][3]); r1.w = hi32(acc[p][3]);
        *(float4*)&Cb[mr * ldc + n0 + tx*4]     = r0;
        *(float4*)&Cb[(mr+1) * ldc + n0 + tx*4] = r1;
    }
}

// ---------------- encoder online-softmax scan over t (per (b,n)) ------------
__global__ void __launch_bounds__(256) enc_scan(float* __restrict__ E)
{
    int gid = blockIdx.x * 256 + threadIdx.x;
    int b = gid >> 9, n = gid & 511;
    float m = -1e30f, s = 0.f;
    float* base = E + (long)b * (64*512) + n;
    for (int t = 0; t < 64; t++) {
        float e  = base[t*512];
        float m2 = fmaxf(m, e);
        s = s * __expf(m - m2) + __expf(e - m2);
        float sc = (t == 0) ? e : __expf(e - m2) / s;
        base[t*512] = sc;
        m = m2;
    }
}

// ---------------- row softmax over n=512, in place ---------------------------
__global__ void __launch_bounds__(256) softmax512(float* __restrict__ E)
{
    __shared__ float red[8];
    __shared__ float fin;
    long row = blockIdx.x;
    float* p = E + row * 512;
    int tid = threadIdx.x;
    int lane = tid & 31, wid = tid >> 5;
    float x0 = p[tid], x1 = p[tid + 256];
    float m = fmaxf(x0, x1);
    #pragma unroll
    for (int o = 16; o; o >>= 1) m = fmaxf(m, __shfl_xor_sync(0xffffffffu, m, o));
    if (lane == 0) red[wid] = m;
    __syncthreads();
    if (tid < 32) {
        float v = (lane < 8) ? red[lane] : -1e30f;
        #pragma unroll
        for (int o = 4; o; o >>= 1) v = fmaxf(v, __shfl_xor_sync(0xffffffffu, v, o));
        if (lane == 0) fin = v;
    }
    __syncthreads();
    float M = fin;
    float e0 = __expf(x0 - M), e1 = __expf(x1 - M);
    float s = e0 + e1;
    #pragma unroll
    for (int o = 16; o; o >>= 1) s += __shfl_xor_sync(0xffffffffu, s, o);
    if (lane == 0) red[wid] = s;
    __syncthreads();
    if (tid < 32) {
        float v = (lane < 8) ? red[lane] : 0.f;
        #pragma unroll
        for (int o = 4; o; o >>= 1) v += __shfl_xor_sync(0xffffffffu, v, o);
        if (lane == 0) fin = v;
    }
    __syncthreads();
    float inv = 1.f / fin;
    p[tid]       = e0 * inv;
    p[tid + 256] = e1 * inv;
}

// ---------------- causal decoder softmax over tp (row len 64), in place ------
__global__ void __launch_bounds__(64) softmax_dec(float* __restrict__ ED)
{
    __shared__ float red[2];
    int row = blockIdx.x;        // b*64 + t
    int t = row & 63;
    int tid = threadIdx.x;       // tp
    float* p = ED + (long)row * 64;
    if (t == 0) { p[tid] = 0.f; return; }
    float x = (tid < t) ? p[tid] : -1e30f;
    int lane = tid & 31, wid = tid >> 5;
    float m = x;
    #pragma unroll
    for (int o = 16; o; o >>= 1) m = fmaxf(m, __shfl_xor_sync(0xffffffffu, m, o));
    if (lane == 0) red[wid] = m;
    __syncthreads();
    float M = fmaxf(red[0], red[1]);
    float e = __expf(x - M);
    float s = e;
    #pragma unroll
    for (int o = 16; o; o >>= 1) s += __shfl_xor_sync(0xffffffffu, s, o);
    __syncthreads();
    if (lane == 0) red[wid] = s;
    __syncthreads();
    float S = red[0] + red[1];
    p[tid] = e / S;
}

// ---------------- host driver ------------------------------------------------
extern "C" void kernel_launch(void* const* d_in, const int* in_sizes, int n_in,
                              void* d_out, int out_size)
{
    (void)in_sizes; (void)n_in; (void)out_size;
    const int*   tok   = (const int*)  d_in[0];
    const float* h_e   = (const float*)d_in[1];
    const float* h0    = (const float*)d_in[2];
    const float* c0    = (const float*)d_in[3];
    const float* W_emb = (const float*)d_in[4];
    const float* W_ih  = (const float*)d_in[5];
    const float* W_hh  = (const float*)d_in[6];
    const float* b_ih  = (const float*)d_in[7];
    const float* b_hh  = (const float*)d_in[8];
    const float* W_enc = (const float*)d_in[9];
    const float* b_enc = (const float*)d_in[10];
    const float* W_dec = (const float*)d_in[11];
    const float* b_dec = (const float*)d_in[12];
    float* out = (float*)d_out;

    float *X, *H, *Q, *QD, *E, *ED, *c, *P;
    __nv_bfloat16 *WHI, *WLO, *hHI, *hLO;
    cudaGetSymbolAddress((void**)&X,  g_X);
    cudaGetSymbolAddress((void**)&H,  g_H);
    cudaGetSymbolAddress((void**)&Q,  g_Q);
    cudaGetSymbolAddress((void**)&QD, g_QD);
    cudaGetSymbolAddress((void**)&E,  g_E);
    cudaGetSymbolAddress((void**)&ED, g_ED);
    cudaGetSymbolAddress((void**)&c,  g_c);
    cudaGetSymbolAddress((void**)&P,  g_P);
    cudaGetSymbolAddress((void**)&WHI, g_WHI);
    cudaGetSymbolAddress((void**)&WLO, g_WLO);
    cudaGetSymbolAddress((void**)&hHI, g_hHI);
    cudaGetSymbolAddress((void**)&hLO, g_hLO);

    // 0) convert W_hh and h0 to bf16 hi/lo
    conv_pair<<<4096,256>>>(W_hh, WHI, WLO, 4096*1024/4);
    conv_pair<<<64,256>>>(h0, hHI, hLO, 64*1024/4);

    // 1) X[t,b,:] = W_emb[tok] @ W_ih^T + b_ih + b_hh    (M=4096,N=4096,K=512)
    gemm_wide<true,false><<<dim3(16,64,1),256>>>(
        W_emb,512,tok, W_ih,512, X,4096, 512, b_ih,b_hh, 0,0,0);

    // 2) sequential LSTM: HMMA split-bf16 gates GEMM (K-split 8) + fin
    for (int t = 0; t < 64; t++) {
        const float* cprev = t ? c : c0;
        hmma_step<<<dim3(32,8,1),256>>>(WHI, WLO, hHI, hLO, P);
        lstm_fin<<<128,128>>>(P, X + (long)t*262144, cprev,
                              c, H + (long)t*65536, out + (long)t*196608,
                              hHI, hLO);
    }

    // 3) Q = H@W_enc^T + b_enc ; QD = H@W_dec^T + b_dec   (M=4096,N=1024,K=1024)
    gemm_wide<false,false><<<dim3(4,64,1),256>>>(
        H,1024,nullptr, W_enc,1024, Q,1024, 1024, b_enc,nullptr, 0,0,0);
    gemm_wide<false,false><<<dim3(4,64,1),256>>>(
        H,1024,nullptr, W_dec,1024, QD,1024, 1024, b_dec,nullptr, 0,0,0);

    // 4) E[b][t][n] = Q[t,b,:] . h_e[n,b,:]   (per-b NT, M=64,N=512,K=1024)
    gemm_wide<false,false><<<dim3(2,1,64),256>>>(
        Q,65536,nullptr, h_e,65536, E,512, 1024, nullptr,nullptr,
        1024,1024,32768);

    // 5) online-softmax scan over t, then row softmax over n (both in place)
    enc_scan<<<128,256>>>(E);
    softmax512<<<4096,256>>>(E);

    // 6) c_e = alpha_e @ h_e -> out[...,1024:2048]  (per-b NN, M=64,N=1024,K=512)
    gemm_wide<false,true><<<dim3(4,1,64),256>>>(
        E,512,nullptr, h_e,65536, out+1024,196608, 512, nullptr,nullptr,
        32768,1024,3072);

    // 7) ED[b][t][tp] = QD[t,b,:] . H[tp,b,:]   (per-b NT, M=64,N=64,K=1024)
    gemm64<false><<<dim3(1,1,64),256>>>(QD,65536, H,65536,
                                        ED,64, 1024, 1024,1024,4096);
    // 8) strictly-causal softmax (zeros at t==0)
    softmax_dec<<<4096,64>>>(ED);
    // 9) cd = alpha_d @ H -> out[...,2048:3072]  (per-b NN, M=64,N=1024,K=64)
    gemm64<true><<<dim3(16,1,64),256>>>(ED,64, H,65536,
                                        out+2048,196608, 64, 4096,1024,3072);
}

// round 16
// speedup vs baseline: 1.3239x; 1.3239x over previous
#include <cuda_runtime.h>
#include <cuda_bf16.h>

typedef unsigned long long u64;
typedef unsigned int u32;

// ---------------- scratch (static device globals; no runtime alloc) ----------
__device__ float g_X [64*64*4096];    // 64 MB: pre-activations X[t,b,4096]
__device__ float g_H [64*64*1024];    // 16 MB: hidden history H[t,b,1024] fp32
__device__ float g_Q [64*64*1024];    // 16 MB: encoder queries
__device__ float g_QD[64*64*1024];    // 16 MB: decoder queries
__device__ float g_E [64*64*512];     //  8 MB: enc scores -> sc -> alpha (in place)
__device__ float g_ED[64*64*64];      //  1 MB: dec scores -> alpha (in place)
__device__ float g_c [64*1024];       // cell state
__device__ float g_P [4*64*4096];     //  4 MB: K-split partials, P[ks][b][4096]
__device__ __nv_bfloat16 g_WHI [4096*1024];   // W_hh bf16 hi
__device__ __nv_bfloat16 g_WLO [4096*1024];   // W_hh bf16 lo
__device__ __nv_bfloat16 g_HHI [64*64*1024];  // H history bf16 hi
__device__ __nv_bfloat16 g_HLO [64*64*1024];  // H history bf16 lo
__device__ __nv_bfloat16 g_h0HI[64*1024];     // h0 bf16 hi
__device__ __nv_bfloat16 g_h0LO[64*1024];     // h0 bf16 lo
__device__ __nv_bfloat16 g_WEHI[1024*1024];   // W_enc hi
__device__ __nv_bfloat16 g_WELO[1024*1024];   // W_enc lo
__device__ __nv_bfloat16 g_WDHI[1024*1024];   // W_dec hi
__device__ __nv_bfloat16 g_WDLO[1024*1024];   // W_dec lo
__device__ __nv_bfloat16 g_EMHI[4096*512];    // gathered embeddings hi
__device__ __nv_bfloat16 g_EMLO[4096*512];    // gathered embeddings lo
__device__ __nv_bfloat16 g_WIHI[4096*512];    // W_ih hi
__device__ __nv_bfloat16 g_WILO[4096*512];    // W_ih lo

// ---------------- f32x2 packed helpers --------------------------------------
__device__ __forceinline__ void fma2(u64& a, u64 x, u64 y){
    asm("fma.rn.f32x2 %0, %1, %2, %0;" : "+l"(a) : "l"(x), "l"(y));
}
__device__ __forceinline__ u64 dup2(float f){
    u32 u = __float_as_uint(f);
    u64 r; asm("mov.b64 %0, {%1, %1};" : "=l"(r) : "r"(u));
    return r;
}
__device__ __forceinline__ float lo32(u64 v){ return __uint_as_float((u32)v); }
__device__ __forceinline__ float hi32(u64 v){ return __uint_as_float((u32)(v>>32)); }

__device__ __forceinline__ u32 smem_u32(const void* p){
    u32 a; asm("{ .reg .u64 t; cvta.to.shared.u64 t, %1; cvt.u32.u64 %0, t; }"
               : "=r"(a) : "l"(p));
    return a;
}

// ---------------- legacy-HMMA helpers (mma.sync, valid on compute_103) -------
#define LDSM4(r, a) \
    asm volatile("ldmatrix.sync.aligned.m8n8.x4.shared.b16 {%0,%1,%2,%3}, [%4];" \
        : "=r"((r)[0]), "=r"((r)[1]), "=r"((r)[2]), "=r"((r)[3]) : "r"(a))

#define MMA16816(d, a, b) \
    asm volatile("mma.sync.aligned.m16n8k16.row.col.f32.bf16.bf16.f32 " \
        "{%0,%1,%2,%3}, {%4,%5,%6,%7}, {%8,%9}, {%0,%1,%2,%3};" \
        : "+f"((d)[0]), "+f"((d)[1]), "+f"((d)[2]), "+f"((d)[3]) \
        : "r"((a)[0]), "r"((a)[1]), "r"((a)[2]), "r"((a)[3]), \
          "r"((b)[0]), "r"((b)[1]))

// ---------------- bf16 hi/lo conversion -------------------------------------
__global__ void __launch_bounds__(256) conv_pair(
    const float* __restrict__ src, __nv_bfloat16* __restrict__ hi,
    __nv_bfloat16* __restrict__ lo, int n4)
{
    int i = blockIdx.x * 256 + threadIdx.x;
    if (i >= n4) return;
    float4 v = ((const float4*)src)[i];
    #pragma unroll
    for (int j = 0; j < 4; j++) {
        float f = (&v.x)[j];
        __nv_bfloat16 h = __float2bfloat16(f);
        hi[i*4 + j] = h;
        lo[i*4 + j] = __float2bfloat16(f - __bfloat162float(h));
    }
}

// gather token embeddings + convert to bf16 hi/lo:  rows (t*64+b) x 512
__global__ void __launch_bounds__(256) conv_gather(
    const float* __restrict__ W_emb, const int* __restrict__ tok,
    __nv_bfloat16* __restrict__ hi, __nv_bfloat16* __restrict__ lo)
{
    int i = blockIdx.x * 256 + threadIdx.x;     // over 4096*128 float4 items
    int r = i >> 7, q = (i & 127) * 4;
    float4 v = *(const float4*)(W_emb + (long)tok[r]*512 + q);
    #pragma unroll
    for (int j = 0; j < 4; j++) {
        float f = (&v.x)[j];
        __nv_bfloat16 h = __float2bfloat16(f);
        hi[(long)r*512 + q + j] = h;
        lo[(long)r*512 + q + j] = __float2bfloat16(f - __bfloat162float(h));
    }
}

// ---------------- HMMA LSTM step GEMM (R13-proven: 8 warps, K-split 4) -------
#define AP 40
#define SM_AHI 0
#define SM_ALO (128*AP)
#define SM_BHI (256*AP)
#define SM_BLO (256*AP + 64*AP)
#define CT_P 66

__global__ void __launch_bounds__(256,2) hmma_step(
    const __nv_bfloat16* __restrict__ Whi, const __nv_bfloat16* __restrict__ Wlo,
    const __nv_bfloat16* __restrict__ hhi, const __nv_bfloat16* __restrict__ hlo,
    float* __restrict__ P)
{
    __shared__ __align__(16) char smraw[33792];
    __nv_bfloat16* Ahi = (__nv_bfloat16*)smraw + SM_AHI;
    __nv_bfloat16* Alo = (__nv_bfloat16*)smraw + SM_ALO;
    __nv_bfloat16* Bhi = (__nv_bfloat16*)smraw + SM_BHI;
    __nv_bfloat16* Blo = (__nv_bfloat16*)smraw + SM_BLO;

    const int tid = threadIdx.x;
    const int w = tid >> 5, l = tid & 31;
    const int m0 = blockIdx.x * 128;
    const int ks = blockIdx.y;
    const int kb = ks * 256;

    float acc[8][4];
    #pragma unroll
    for (int nj = 0; nj < 8; nj++)
        #pragma unroll
        for (int q = 0; q < 4; q++) acc[nj][q] = 0.f;

    const int arow = tid >> 1, ahalf = tid & 1;
    const uint4* gAh = (const uint4*)(Whi + (long)(m0 + arow)*1024 + kb);
    const uint4* gAl = (const uint4*)(Wlo + (long)(m0 + arow)*1024 + kb);
    uint4* sAh = (uint4*)(Ahi + arow*AP);
    uint4* sAl = (uint4*)(Alo + arow*AP);
    const int brow = tid >> 2, bp = tid & 3;
    const uint4* gBh = (const uint4*)(hhi + (long)brow*1024 + kb);
    const uint4* gBl = (const uint4*)(hlo + (long)brow*1024 + kb);
    uint4* sBh = (uint4*)(Bhi + brow*AP);
    uint4* sBl = (uint4*)(Blo + brow*AP);

    const int a_r = (l & 15);
    const int a_c = (l & 16) ? 8 : 0;
    const int b_r = (l & 7);
    const int b_c = (l & 8) ? 8 : 0;

    uint4 pAh[2], pAl[2], pBh, pBl;
    pAh[0] = gAh[ahalf*2]; pAh[1] = gAh[ahalf*2 + 1];
    pAl[0] = gAl[ahalf*2]; pAl[1] = gAl[ahalf*2 + 1];
    pBh = gBh[bp]; pBl = gBl[bp];

    for (int kc = 0; kc < 8; kc++) {
        __syncthreads();
        sAh[ahalf*2] = pAh[0]; sAh[ahalf*2 + 1] = pAh[1];
        sAl[ahalf*2] = pAl[0]; sAl[ahalf*2 + 1] = pAl[1];
        sBh[bp] = pBh; sBl[bp] = pBl;
        __syncthreads();
        if (kc + 1 < 8) {
            int base = (kc + 1) * 4;
            pAh[0] = gAh[base + ahalf*2]; pAh[1] = gAh[base + ahalf*2 + 1];
            pAl[0] = gAl[base + ahalf*2]; pAl[1] = gAl[base + ahalf*2 + 1];
            pBh = gBh[base + bp]; pBl = gBl[base + bp];
        }
        #pragma unroll
        for (int k16 = 0; k16 < 2; k16++) {
            const int k0 = k16 * 16;
            u32 ah[4], al[4], bh[8][2], bl[8][2];
            {
                int row = w*16 + a_r;
                LDSM4(ah, smem_u32(Ahi + row*AP + k0 + a_c));
                LDSM4(al, smem_u32(Alo + row*AP + k0 + a_c));
            }
            #pragma unroll
            for (int jj = 0; jj < 4; jj++) {
                int n = ((l < 16) ? jj*2 : jj*2+1)*8 + b_r;
                u32 r4[4];
                LDSM4(r4, smem_u32(Bhi + n*AP + k0 + b_c));
                bh[jj*2][0] = r4[0]; bh[jj*2][1] = r4[1];
                bh[jj*2+1][0] = r4[2]; bh[jj*2+1][1] = r4[3];
                LDSM4(r4, smem_u32(Blo + n*AP + k0 + b_c));
                bl[jj*2][0] = r4[0]; bl[jj*2][1] = r4[1];
                bl[jj*2+1][0] = r4[2]; bl[jj*2+1][1] = r4[3];
            }
            #pragma unroll
            for (int nj = 0; nj < 8; nj++) {
                MMA16816(acc[nj], ah, bh[nj]);
                MMA16816(acc[nj], ah, bl[nj]);
                MMA16816(acc[nj], al, bh[nj]);
            }
        }
    }

    __syncthreads();
    float* Ct = (float*)smraw;
    {
        int row = w*16 + (l >> 2);
        #pragma unroll
        for (int nj = 0; nj < 8; nj++) {
            int colb = nj*8 + (l & 3)*2;
            *(float2*)&Ct[row*CT_P + colb]     = make_float2(acc[nj][0], acc[nj][1]);
            *(float2*)&Ct[(row+8)*CT_P + colb] = make_float2(acc[nj][2], acc[nj][3]);
        }
    }
    __syncthreads();
    {
        int b = tid >> 2, q = tid & 3;
        float* dst = P + ((long)ks*64 + b)*4096 + m0 + q*32;
        #pragma unroll
        for (int i = 0; i < 8; i++) {
            int m = q*32 + i*4;
            float4 v;
            v.x = Ct[(m+0)*CT_P + b];
            v.y = Ct[(m+1)*CT_P + b];
            v.z = Ct[(m+2)*CT_P + b];
            v.w = Ct[(m+3)*CT_P + b];
            *(float4*)(dst + i*4) = v;
        }
    }
}

// ---------------- generic HMMA GEMM with direct-store epilogue ---------------
// C[m,n] = sum_k A[m,k]*B[n,k] + bias1[n] + bias2[n], split-bf16 3-product.
// grid (m-tiles of 128, n-tiles of 64), 256 threads. K multiple of 32.
__global__ void __launch_bounds__(256,2) hmma_q(
    const __nv_bfloat16* __restrict__ Ahi_g, const __nv_bfloat16* __restrict__ Alo_g,
    const __nv_bfloat16* __restrict__ Bhi_g, const __nv_bfloat16* __restrict__ Blo_g,
    const float* __restrict__ bias1, const float* __restrict__ bias2,
    float* __restrict__ C, int K, int ldc)
{
    __shared__ __align__(16) char smraw[30720];
    __nv_bfloat16* Ahi = (__nv_bfloat16*)smraw + SM_AHI;
    __nv_bfloat16* Alo = (__nv_bfloat16*)smraw + SM_ALO;
    __nv_bfloat16* Bhi = (__nv_bfloat16*)smraw + SM_BHI;
    __nv_bfloat16* Blo = (__nv_bfloat16*)smraw + SM_BLO;

    const int tid = threadIdx.x;
    const int w = tid >> 5, l = tid & 31;
    const int m0 = blockIdx.x * 128;
    const int n0 = blockIdx.y * 64;
    const int kcnt = K >> 5;

    float acc[8][4];
    #pragma unroll
    for (int nj = 0; nj < 8; nj++)
        #pragma unroll
        for (int q = 0; q < 4; q++) acc[nj][q] = 0.f;

    const int arow = tid >> 1, ahalf = tid & 1;
    const uint4* gAh = (const uint4*)(Ahi_g + (long)(m0 + arow)*K);
    const uint4* gAl = (const uint4*)(Alo_g + (long)(m0 + arow)*K);
    uint4* sAh = (uint4*)(Ahi + arow*AP);
    uint4* sAl = (uint4*)(Alo + arow*AP);
    const int brow = tid >> 2, bp = tid & 3;
    const uint4* gBh = (const uint4*)(Bhi_g + (long)(n0 + brow)*K);
    const uint4* gBl = (const uint4*)(Blo_g + (long)(n0 + brow)*K);
    uint4* sBh = (uint4*)(Bhi + brow*AP);
    uint4* sBl = (uint4*)(Blo + brow*AP);

    const int a_r = (l & 15);
    const int a_c = (l & 16) ? 8 : 0;
    const int b_r = (l & 7);
    const int b_c = (l & 8) ? 8 : 0;

    uint4 pAh[2], pAl[2], pBh, pBl;
    pAh[0] = gAh[ahalf*2]; pAh[1] = gAh[ahalf*2 + 1];
    pAl[0] = gAl[ahalf*2]; pAl[1] = gAl[ahalf*2 + 1];
    pBh = gBh[bp]; pBl = gBl[bp];

    for (int kc = 0; kc < kcnt; kc++) {
        __syncthreads();
        sAh[ahalf*2] = pAh[0]; sAh[ahalf*2 + 1] = pAh[1];
        sAl[ahalf*2] = pAl[0]; sAl[ahalf*2 + 1] = pAl[1];
        sBh[bp] = pBh; sBl[bp] = pBl;
        __syncthreads();
        if (kc + 1 < kcnt) {
            int base = (kc + 1) * 4;
            pAh[0] = gAh[base + ahalf*2]; pAh[1] = gAh[base + ahalf*2 + 1];
            pAl[0] = gAl[base + ahalf*2]; pAl[1] = gAl[base + ahalf*2 + 1];
            pBh = gBh[base + bp]; pBl = gBl[base + bp];
        }
        #pragma unroll
        for (int k16 = 0; k16 < 2; k16++) {
            const int k0 = k16 * 16;
            u32 ah[4], al[4], bh[8][2], bl[8][2];
            {
                int row = w*16 + a_r;
                LDSM4(ah, smem_u32(Ahi + row*AP + k0 + a_c));
                LDSM4(al, smem_u32(Alo + row*AP + k0 + a_c));
            }
            #pragma unroll
            for (int jj = 0; jj < 4; jj++) {
                int n = ((l < 16) ? jj*2 : jj*2+1)*8 + b_r;
                u32 r4[4];
                LDSM4(r4, smem_u32(Bhi + n*AP + k0 + b_c));
                bh[jj*2][0] = r4[0]; bh[jj*2][1] = r4[1];
                bh[jj*2+1][0] = r4[2]; bh[jj*2+1][1] = r4[3];
                LDSM4(r4, smem_u32(Blo + n*AP + k0 + b_c));
                bl[jj*2][0] = r4[0]; bl[jj*2][1] = r4[1];
                bl[jj*2+1][0] = r4[2]; bl[jj*2+1][1] = r4[3];
            }
            #pragma unroll
            for (int nj = 0; nj < 8; nj++) {
                MMA16816(acc[nj], ah, bh[nj]);
                MMA16816(acc[nj], ah, bl[nj]);
                MMA16816(acc[nj], al, bh[nj]);
            }
        }
    }

    // direct-store epilogue: C[m0+row][n0+col] (+bias)
    {
        int row = w*16 + (l >> 2);
        float* Cr0 = C + (long)(m0 + row)*ldc;
        float* Cr1 = Cr0 + 8*ldc;
        #pragma unroll
        for (int nj = 0; nj < 8; nj++) {
            int cb = n0 + nj*8 + (l & 3)*2;
            float b0 = 0.f, b1 = 0.f;
            if (bias1) { b0 = bias1[cb]; b1 = bias1[cb+1]; }
            if (bias2) { b0 += bias2[cb]; b1 += bias2[cb+1]; }
            *(float2*)&Cr0[cb] = make_float2(acc[nj][0] + b0, acc[nj][1] + b1);
            *(float2*)&Cr1[cb] = make_float2(acc[nj][2] + b0, acc[nj][3] + b1);
        }
    }
}

// ---------------- LSTM fin: reduce 4 partials + elementwise + bf16 history ---
__global__ void __launch_bounds__(128) lstm_fin(
    const float* __restrict__ P, const float* __restrict__ X,
    const float* __restrict__ cprev,
    float* __restrict__ cnew, float* __restrict__ Hout,
    float* __restrict__ outp,
    __nv_bfloat16* __restrict__ hHI, __nv_bfloat16* __restrict__ hLO)
{
    int idx = blockIdx.x * 128 + threadIdx.x;   // 0..16383
    int b  = idx >> 8;
    int dq = (idx & 255) * 4;

    float4 g[4];
    #pragma unroll
    for (int gate = 0; gate < 4; gate++) {
        long off = (long)b * 4096 + gate * 1024 + dq;
        float4 v = *(const float4*)&X[off];
        #pragma unroll
        for (int ks = 0; ks < 4; ks++) {
            float4 p = *(const float4*)&P[(long)ks * (64*4096) + off];
            v.x += p.x; v.y += p.y; v.z += p.z; v.w += p.w;
        }
        g[gate] = v;
    }
    float4 co = *(const float4*)&cprev[b*1024 + dq];
    float4 cn, hn;
    #pragma unroll
    for (int j = 0; j < 4; j++) {
        float iv = (&g[0].x)[j], fv = (&g[1].x)[j];
        float gv = (&g[2].x)[j], ov = (&g[3].x)[j];
        float si = 1.f / (1.f + __expf(-iv));
        float sf = 1.f / (1.f + __expf(-fv));
        float so = 1.f / (1.f + __expf(-ov));
        float tg = 2.f / (1.f + __expf(-2.f*gv)) - 1.f;
        float cc = sf * (&co.x)[j] + si * tg;
        float tc = 2.f / (1.f + __expf(-2.f*cc)) - 1.f;
        (&cn.x)[j] = cc;
        (&hn.x)[j] = so * tc;
    }
    *(float4*)&cnew[b*1024 + dq] = cn;
    *(float4*)&Hout[b*1024 + dq] = hn;
    *(float4*)&outp[(long)b*3072 + dq] = hn;
    #pragma unroll
    for (int j = 0; j < 4; j++) {
        float hv = (&hn.x)[j];
        __nv_bfloat16 h = __float2bfloat16(hv);
        hHI[b*1024 + dq + j] = h;
        hLO[b*1024 + dq + j] = __float2bfloat16(hv - __bfloat162float(h));
    }
}

// ---------------- wide GEMM (R7-proven; E and c_e) ---------------------------
template<bool GATHER, bool BNN>
__global__ void __launch_bounds__(256) gemm_wide(
    const float* __restrict__ A, long lda, const int* __restrict__ ridx,
    const float* __restrict__ B, long ldb,
    float* __restrict__ C, long ldc, int K,
    const float* __restrict__ bias1, const float* __restrict__ bias2,
    long bsA, long bsB, long bsC)
{
    __shared__ float At[16][68];
    __shared__ float Bt[16][260];
    const int tid = threadIdx.x;
    const int tx = tid & 31;
    const int ty = tid >> 5;
    const int n0 = blockIdx.x * 256;
    const int m0 = blockIdx.y * 64;
    const long z = blockIdx.z;

    const int arow = tid >> 2, akq = tid & 3;
    const float* Arow;
    {
        const float* Ab = A + z * bsA;
        long mrow = m0 + arow;
        if (GATHER) mrow = ridx[mrow];
        Arow = Ab + mrow * lda + akq * 4;
    }
    const int brow = tid >> 1, bq = tid & 1;
    const float* Brow0 = nullptr; const float* Brow1 = nullptr;
    const int bk = tid >> 4, bn = tid & 15;
    const float* Bk = nullptr;
    {
        const float* Bb = B + z * bsB;
        if (BNN) Bk = Bb + (long)bk * ldb + n0 + bn * 16;
        else {
            Brow0 = Bb + (long)(n0 + brow)       * ldb + bq * 8;
            Brow1 = Bb + (long)(n0 + brow + 128) * ldb + bq * 8;
        }
    }

    u64 acc[4][8];
    #pragma unroll
    for (int i = 0; i < 4; i++)
        #pragma unroll
        for (int j = 0; j < 8; j++) acc[i][j] = 0ull;

    float4 ra = *(const float4*)Arow;
    float4 pb0, pb1, pb2, pb3;
    if (BNN) {
        pb0 = *(const float4*)(Bk);
        pb1 = *(const float4*)(Bk + 4);
        pb2 = *(const float4*)(Bk + 8);
        pb3 = *(const float4*)(Bk + 12);
    } else {
        pb0 = *(const float4*)(Brow0);
        pb1 = *(const float4*)(Brow0 + 4);
        pb2 = *(const float4*)(Brow1);
        pb3 = *(const float4*)(Brow1 + 4);
    }

    for (int k0 = 0; k0 < K; k0 += 16) {
        __syncthreads();
        At[akq*4+0][arow] = ra.x;
        At[akq*4+1][arow] = ra.y;
        At[akq*4+2][arow] = ra.z;
        At[akq*4+3][arow] = ra.w;
        if (BNN) {
            *(float4*)&Bt[bk][bn*16 + 0]  = pb0;
            *(float4*)&Bt[bk][bn*16 + 4]  = pb1;
            *(float4*)&Bt[bk][bn*16 + 8]  = pb2;
            *(float4*)&Bt[bk][bn*16 + 12] = pb3;
        } else {
            Bt[bq*8+0][brow] = pb0.x; Bt[bq*8+1][brow] = pb0.y;
            Bt[bq*8+2][brow] = pb0.z; Bt[bq*8+3][brow] = pb0.w;
            Bt[bq*8+4][brow] = pb1.x; Bt[bq*8+5][brow] = pb1.y;
            Bt[bq*8+6][brow] = pb1.z; Bt[bq*8+7][brow] = pb1.w;
            Bt[bq*8+0][brow+128] = pb2.x; Bt[bq*8+1][brow+128] = pb2.y;
            Bt[bq*8+2][brow+128] = pb2.z; Bt[bq*8+3][brow+128] = pb2.w;
            Bt[bq*8+4][brow+128] = pb3.x; Bt[bq*8+5][brow+128] = pb3.y;
            Bt[bq*8+6][brow+128] = pb3.z; Bt[bq*8+7][brow+128] = pb3.w;
        }
        __syncthreads();
        if (k0 + 16 < K) {
            ra = *(const float4*)(Arow + k0 + 16);
            if (BNN) {
                const float* p = Bk + (long)(k0 + 16) * ldb;
                pb0 = *(const float4*)(p);
                pb1 = *(const float4*)(p + 4);
                pb2 = *(const float4*)(p + 8);
                pb3 = *(const float4*)(p + 12);
            } else {
                pb0 = *(const float4*)(Brow0 + k0 + 16);
                pb1 = *(const float4*)(Brow0 + k0 + 20);
                pb2 = *(const float4*)(Brow1 + k0 + 16);
                pb3 = *(const float4*)(Brow1 + k0 + 20);
            }
        }
        #pragma unroll
        for (int k = 0; k < 16; k++) {
            u64 a0 = *(const u64*)&At[k][ty*8];
            u64 a1 = *(const u64*)&At[k][ty*8+2];
            u64 a2 = *(const u64*)&At[k][ty*8+4];
            u64 a3 = *(const u64*)&At[k][ty*8+6];
            #pragma unroll
            for (int j = 0; j < 8; j++) {
                u64 bd = dup2(Bt[k][tx + 32*j]);
                fma2(acc[0][j], a0, bd);
                fma2(acc[1][j], a1, bd);
                fma2(acc[2][j], a2, bd);
                fma2(acc[3][j], a3, bd);
            }
        }
    }

    float bn8[8];
    #pragma unroll
    for (int j = 0; j < 8; j++) {
        int n = n0 + tx + 32*j;
        float v = 0.f;
        if (bias1) v += bias1[n];
        if (bias2) v += bias2[n];
        bn8[j] = v;
    }
    float* Cb = C + z * bsC;
    #pragma unroll
    for (int i = 0; i < 4; i++) {
        long r = m0 + ty*8 + 2*i;
        #pragma unroll
        for (int j = 0; j < 8; j++) {
            int n = n0 + tx + 32*j;
            Cb[r*ldc + n]     = lo32(acc[i][j]) + bn8[j];
            Cb[(r+1)*ldc + n] = hi32(acc[i][j]) + bn8[j];
        }
    }
}

// ---------------- small 64x64 NT/NN GEMM for ED / cd -------------------------
template<bool BNN>
__global__ void __launch_bounds__(256) gemm64(
    const float* __restrict__ A, long lda,
    const float* __restrict__ B, long ldb,
    float* __restrict__ C, long ldc, int K,
    long bsA, long bsB, long bsC)
{
    __shared__ float At[16][68];
    __shared__ float Bt[16][68];
    const int tid = threadIdx.x;
    const int tx = tid & 15, ty = tid >> 4;
    const int m0 = blockIdx.y * 64;
    const int n0 = blockIdx.x * 64;
    const long z = blockIdx.z;

    const int arow = tid >> 2, akq = tid & 3;
    const float* Arow = A + z*bsA + (long)(m0 + arow)*lda + akq*4;
    const float* Brow;
    int bk = 0, bnq = 0, brow = 0, bkq = 0;
    {
        const float* Bb = B + z * bsB;
        if (BNN) { bk = tid >> 4; bnq = tid & 15; Brow = Bb + (long)bk * ldb + n0 + bnq * 4; }
        else     { brow = tid >> 2; bkq = tid & 3; Brow = Bb + (long)(n0 + brow) * ldb + bkq * 4; }
    }

    u64 acc[2][4];
    #pragma unroll
    for (int p = 0; p < 2; p++)
        #pragma unroll
        for (int j = 0; j < 4; j++) acc[p][j] = 0ull;

    float4 ra = *(const float4*)(Arow);
    float4 rb = *(const float4*)(Brow);

    for (int k0 = 0; k0 < K; k0 += 16) {
        __syncthreads();
        At[akq*4+0][arow] = ra.x;
        At[akq*4+1][arow] = ra.y;
        At[akq*4+2][arow] = ra.z;
        At[akq*4+3][arow] = ra.w;
        if (BNN) {
            *(float4*)&Bt[bk][bnq*4] = rb;
        } else {
            Bt[bkq*4+0][brow] = rb.x;
            Bt[bkq*4+1][brow] = rb.y;
            Bt[bkq*4+2][brow] = rb.z;
            Bt[bkq*4+3][brow] = rb.w;
        }
        __syncthreads();
        if (k0 + 16 < K) {
            ra = *(const float4*)(Arow + k0 + 16);
            rb = BNN ? *(const float4*)(Brow + (long)(k0 + 16) * ldb)
                     : *(const float4*)(Brow + k0 + 16);
        }
        #pragma unroll
        for (int k = 0; k < 16; k++) {
            u64 a01 = *(const u64*)&At[k][ty*4];
            u64 a23 = *(const u64*)&At[k][ty*4+2];
            float4 bv = *(const float4*)&Bt[k][tx*4];
            u64 b0 = dup2(bv.x), b1 = dup2(bv.y), b2 = dup2(bv.z), b3 = dup2(bv.w);
            fma2(acc[0][0], a01, b0); fma2(acc[1][0], a23, b0);
            fma2(acc[0][1], a01, b1); fma2(acc[1][1], a23, b1);
            fma2(acc[0][2], a01, b2); fma2(acc[1][2], a23, b2);
            fma2(acc[0][3], a01, b3); fma2(acc[1][3], a23, b3);
        }
    }

    float* Cb = C + z * bsC;
    #pragma unroll
    for (int p = 0; p < 2; p++) {
        long mr = m0 + ty*4 + 2*p;
        float4 r0, r1;
        r0.x = lo32(acc[p][0]); r1.x = hi32(acc[p][0]);
        r0.y = lo32(acc[p][1]); r1.y = hi32(acc[p][1]);
        r0.z = lo32(acc[p][2]); r1.z = hi32(acc[p][2]);
        r0.w = lo32(acc[p][3]); r1.w = hi32(acc[p][3]);
        *(float4*)&Cb[mr * ldc + n0 + tx*4]     = r0;
        *(float4*)&Cb[(mr+1) * ldc + n0 + tx*4] = r1;
    }
}

// ---------------- encoder online-softmax scan over t (per (b,n)) ------------
__global__ void __launch_bounds__(256) enc_scan(float* __restrict__ E)
{
    int gid = blockIdx.x * 256 + threadIdx.x;
    int b = gid >> 9, n = gid & 511;
    float m = -1e30f, s = 0.f;
    float* base = E + (long)b * (64*512) + n;
    for (int t = 0; t < 64; t++) {
        float e  = base[t*512];
        float m2 = fmaxf(m, e);
        s = s * __expf(m - m2) + __expf(e - m2);
        float sc = (t == 0) ? e : __expf(e - m2) / s;
        base[t*512] = sc;
        m = m2;
    }
}

// ---------------- row softmax over n=512, in place ---------------------------
__global__ void __launch_bounds__(256) softmax512(float* __restrict__ E)
{
    __shared__ float red[8];
    __shared__ float fin;
    long row = blockIdx.x;
    float* p = E + row * 512;
    int tid = threadIdx.x;
    int lane = tid & 31, wid = tid >> 5;
    float x0 = p[tid], x1 = p[tid + 256];
    float m = fmaxf(x0, x1);
    #pragma unroll
    for (int o = 16; o; o >>= 1) m = fmaxf(m, __shfl_xor_sync(0xffffffffu, m, o));
    if (lane == 0) red[wid] = m;
    __syncthreads();
    if (tid < 32) {
        float v = (lane < 8) ? red[lane] : -1e30f;
        #pragma unroll
        for (int o = 4; o; o >>= 1) v = fmaxf(v, __shfl_xor_sync(0xffffffffu, v, o));
        if (lane == 0) fin = v;
    }
    __syncthreads();
    float M = fin;
    float e0 = __expf(x0 - M), e1 = __expf(x1 - M);
    float s = e0 + e1;
    #pragma unroll
    for (int o = 16; o; o >>= 1) s += __shfl_xor_sync(0xffffffffu, s, o);
    if (lane == 0) red[wid] = s;
    __syncthreads();
    if (tid < 32) {
        float v = (lane < 8) ? red[lane] : 0.f;
        #pragma unroll
        for (int o = 4; o; o >>= 1) v += __shfl_xor_sync(0xffffffffu, v, o);
        if (lane == 0) fin = v;
    }
    __syncthreads();
    float inv = 1.f / fin;
    p[tid]       = e0 * inv;
    p[tid + 256] = e1 * inv;
}

// ---------------- causal decoder softmax over tp (row len 64), in place ------
__global__ void __launch_bounds__(64) softmax_dec(float* __restrict__ ED)
{
    __shared__ float red[2];
    int row = blockIdx.x;        // b*64 + t
    int t = row & 63;
    int tid = threadIdx.x;       // tp
    float* p = ED + (long)row * 64;
    if (t == 0) { p[tid] = 0.f; return; }
    float x = (tid < t) ? p[tid] : -1e30f;
    int lane = tid & 31, wid = tid >> 5;
    float m = x;
    #pragma unroll
    for (int o = 16; o; o >>= 1) m = fmaxf(m, __shfl_xor_sync(0xffffffffu, m, o));
    if (lane == 0) red[wid] = m;
    __syncthreads();
    float M = fmaxf(red[0], red[1]);
    float e = __expf(x - M);
    float s = e;
    #pragma unroll
    for (int o = 16; o; o >>= 1) s += __shfl_xor_sync(0xffffffffu, s, o);
    __syncthreads();
    if (lane == 0) red[wid] = s;
    __syncthreads();
    float S = red[0] + red[1];
    p[tid] = e / S;
}

// ---------------- host driver ------------------------------------------------
extern "C" void kernel_launch(void* const* d_in, const int* in_sizes, int n_in,
                              void* d_out, int out_size)
{
    (void)in_sizes; (void)n_in; (void)out_size;
    const int*   tok   = (const int*)  d_in[0];
    const float* h_e   = (const float*)d_in[1];
    const float* h0    = (const float*)d_in[2];
    const float* c0    = (const float*)d_in[3];
    const float* W_emb = (const float*)d_in[4];
    const float* W_ih  = (const float*)d_in[5];
    const float* W_hh  = (const float*)d_in[6];
    const float* b_ih  = (const float*)d_in[7];
    const float* b_hh  = (const float*)d_in[8];
    const float* W_enc = (const float*)d_in[9];
    const float* b_enc = (const float*)d_in[10];
    const float* W_dec = (const float*)d_in[11];
    const float* b_dec = (const float*)d_in[12];
    float* out = (float*)d_out;

    float *X, *H, *Q, *QD, *E, *ED, *c, *P;
    __nv_bfloat16 *WHI, *WLO, *HHI, *HLO, *h0HI, *h0LO;
    __nv_bfloat16 *WEHI, *WELO, *WDHI, *WDLO, *EMHI, *EMLO, *WIHI, *WILO;
    cudaGetSymbolAddress((void**)&X,  g_X);
    cudaGetSymbolAddress((void**)&H,  g_H);
    cudaGetSymbolAddress((void**)&Q,  g_Q);
    cudaGetSymbolAddress((void**)&QD, g_QD);
    cudaGetSymbolAddress((void**)&E,  g_E);
    cudaGetSymbolAddress((void**)&ED, g_ED);
    cudaGetSymbolAddress((void**)&c,  g_c);
    cudaGetSymbolAddress((void**)&P,  g_P);
    cudaGetSymbolAddress((void**)&WHI, g_WHI);
    cudaGetSymbolAddress((void**)&WLO, g_WLO);
    cudaGetSymbolAddress((void**)&HHI, g_HHI);
    cudaGetSymbolAddress((void**)&HLO, g_HLO);
    cudaGetSymbolAddress((void**)&h0HI, g_h0HI);
    cudaGetSymbolAddress((void**)&h0LO, g_h0LO);
    cudaGetSymbolAddress((void**)&WEHI, g_WEHI);
    cudaGetSymbolAddress((void**)&WELO, g_WELO);
    cudaGetSymbolAddress((void**)&WDHI, g_WDHI);
    cudaGetSymbolAddress((void**)&WDLO, g_WDLO);
    cudaGetSymbolAddress((void**)&EMHI, g_EMHI);
    cudaGetSymbolAddress((void**)&EMLO, g_EMLO);
    cudaGetSymbolAddress((void**)&WIHI, g_WIHI);
    cudaGetSymbolAddress((void**)&WILO, g_WILO);

    // 0) conversions: W_hh, h0, W_enc, W_dec, W_ih, gathered embeddings
    conv_pair<<<4096,256>>>(W_hh, WHI, WLO, 4096*1024/4);
    conv_pair<<<64,256>>>(h0, h0HI, h0LO, 64*1024/4);
    conv_pair<<<1024,256>>>(W_enc, WEHI, WELO, 1024*1024/4);
    conv_pair<<<1024,256>>>(W_dec, WDHI, WDLO, 1024*1024/4);
    conv_pair<<<2048,256>>>(W_ih, WIHI, WILO, 4096*512/4);
    conv_gather<<<2048,256>>>(W_emb, tok, EMHI, EMLO);

    // 1) X = emb @ W_ih^T + b_ih + b_hh   (HMMA; M=4096,N=4096,K=512)
    hmma_q<<<dim3(32,64,1),256>>>(EMHI, EMLO, WIHI, WILO,
                                  b_ih, b_hh, X, 512, 4096);

    // 2) sequential LSTM: HMMA split-bf16 gates GEMM (K-split 4) + fin
    for (int t = 0; t < 64; t++) {
        const float* cprev = t ? c : c0;
        const __nv_bfloat16* hhi = t ? HHI + (long)(t-1)*65536 : h0HI;
        const __nv_bfloat16* hlo = t ? HLO + (long)(t-1)*65536 : h0LO;
        hmma_step<<<dim3(32,4,1),256>>>(WHI, WLO, hhi, hlo, P);
        lstm_fin<<<128,128>>>(P, X + (long)t*262144, cprev,
                              c, H + (long)t*65536, out + (long)t*196608,
                              HHI + (long)t*65536, HLO + (long)t*65536);
    }

    // 3) Q = H@W_enc^T + b_enc ; QD = H@W_dec^T + b_dec  (HMMA; M=4096,N=1024,K=1024)
    hmma_q<<<dim3(32,16,1),256>>>(HHI, HLO, WEHI, WELO,
                                  b_enc, nullptr, Q, 1024, 1024);
    hmma_q<<<dim3(32,16,1),256>>>(HHI, HLO, WDHI, WDLO,
                                  b_dec, nullptr, QD, 1024, 1024);

    // 4) E[b][t][n] = Q[t,b,:] . h_e[n,b,:]   (per-b NT, M=64,N=512,K=1024)
    gemm_wide<false,false><<<dim3(2,1,64),256>>>(
        Q,65536,nullptr, h_e,65536, E,512, 1024, nullptr,nullptr,
        1024,1024,32768);

    // 5) online-softmax scan over t, then row softmax over n (both in place)
    enc_scan<<<128,256>>>(E);
    softmax512<<<4096,256>>>(E);

    // 6) c_e = alpha_e @ h_e -> out[...,1024:2048]  (per-b NN, M=64,N=1024,K=512)
    gemm_wide<false,true><<<dim3(4,1,64),256>>>(
        E,512,nullptr, h_e,65536, out+1024,196608, 512, nullptr,nullptr,
        32768,1024,3072);

    // 7) ED[b][t][tp] = QD[t,b,:] . H[tp,b,:]   (per-b NT, M=64,N=64,K=1024)
    gemm64<false><<<dim3(1,1,64),256>>>(QD,65536, H,65536,
                                        ED,64, 1024, 1024,1024,4096);
    // 8) strictly-causal softmax (zeros at t==0)
    softmax_dec<<<4096,64>>>(ED);
    // 9) cd = alpha_d @ H -> out[...,2048:3072]  (per-b NN, M=64,N=1024,K=64)
    gemm64<true><<<dim3(16,1,64),256>>>(ED,64, H,65536,
                                        out+2048,196608, 64, 4096,1024,3072);
}